// round 8
// baseline (speedup 1.0000x reference)
#include <cuda_runtime.h>

// out[i,c] = 8! * sum_j ( relu(x @ W1 + b1) @ W2 + b2 )[j,c]   (row-constant)
//
// R8: 4-CTA cluster (one D-slice of 128 per CTA, 4 warps/CTA -> 1 warp/SMSP
// on 4 SMs). Per-CTA local reduce of packed f32x2 partials, DSMEM push of
// 160 packed values into CTA0, cluster.sync, CTA0 does bias/relu + tail.
// All reduction trees fixed-order (bitwise identical to R7).

static constexpr int N = 9;
static constexpr int D = 512;
static constexpr int H = 32;
static constexpr int CLUSTER = 4;
static constexpr int THREADS = 128;        // per CTA, 4 warps
static constexpr int WPC = 4;              // warps per CTA
static constexpr int DSLICE = D / CLUSTER; // 128 d-columns per CTA
static constexpr int DPW = DSLICE / WPC;   // 32 d-values per warp
static constexpr int XPAD = 12;            // floats per xT row (48B)
static constexpr int PAIRS = 5;            // (0,1)(2,3)(4,5)(6,7)(8,pad)
static constexpr int SLOTS = PAIRS * H;    // 160 packed slots
static constexpr float FACT8 = 40320.0f;   // (N-1)!

typedef unsigned long long u64;

__device__ __forceinline__ unsigned smem_u32(const void* p) {
    unsigned a;
    asm("{ .reg .u64 t; cvta.to.shared.u64 t, %1; cvt.u32.u64 %0, t; }"
        : "=r"(a) : "l"(p));
    return a;
}

__global__ void __launch_bounds__(THREADS, 1) __cluster_dims__(CLUSTER, 1, 1)
sym_kernel(const float* __restrict__ x,
           const float* __restrict__ W1,
           const float* __restrict__ b1,
           const float* __restrict__ W2,
           const float* __restrict__ b2,
           float* __restrict__ out) {
    __shared__ __align__(16) float xT[DSLICE * XPAD];   // xT[d][r], this slice
    __shared__ __align__(16) u64 psum[WPC * SLOTS];     // per-warp packed partials
    __shared__ __align__(16) u64 gather[CLUSTER * SLOTS]; // CTA0: per-CTA partials
    __shared__ __align__(16) float h[N * H];

    const int t = threadIdx.x;
    const int w = t >> 5;   // warp 0..3
    const int k = t & 31;   // lane
    unsigned rank;
    asm("mov.u32 %0, %%cluster_ctarank;" : "=r"(rank));
    const int dbase = rank * DSLICE;

    // ---- per-warp prefetch ----
    // x transpose: thread t owns column d = dbase + t (coalesced LDGs)
#pragma unroll
    for (int r = 0; r < N; r++)
        xT[t * XPAD + r] = x[r * D + dbase + t];
    xT[t * XPAD + 9] = 0.0f;   // pad read by the packed row-8 accumulator

    // W1 chunk -> packed (wv,wv) registers
    u64 wpack[DPW];
    const float* W1p = W1 + (dbase + w * DPW) * H + k;
#pragma unroll
    for (int i = 0; i < DPW; i++) {
        unsigned wu = __float_as_uint(W1p[i * H]);
        asm("mov.b64 %0, {%1, %1};" : "=l"(wpack[i]) : "r"(wu));
    }

    // CTA0-only tail operands
    float b1r = 0.f, w2c = 0.f, b2c = 0.f;
    if (rank == 0) {
        b1r = b1[k];            // slot kk == lane k in both finish calls
        w2c = W2[k * 4 + w];    // W2[k][c], warp w = column c
        b2c = b2[w];
    }
    __syncwarp();   // xT slice is produced/consumed by this warp only

    // ---- rank-1-update partial dots: 5 packed f32x2 accumulators ----
    u64 a01 = 0, a23 = 0, a45 = 0, a67 = 0, a89 = 0;
    const float* xrow = xT + (w * DPW) * XPAD;
#pragma unroll
    for (int i = 0; i < DPW; i++) {
        const float* xp = xrow + i * XPAD;              // 48B-aligned
        ulonglong2 p0 = *(const ulonglong2*)(xp);       // rows 0..3 (bcast)
        u64 p2 = *(const u64*)(xp + 4);                 // rows 4,5
        u64 p3 = *(const u64*)(xp + 6);                 // rows 6,7
        u64 p4 = *(const u64*)(xp + 8);                 // rows 8,pad
        u64 ww = wpack[i];
        asm("fma.rn.f32x2 %0, %1, %2, %0;" : "+l"(a01) : "l"(p0.x), "l"(ww));
        asm("fma.rn.f32x2 %0, %1, %2, %0;" : "+l"(a23) : "l"(p0.y), "l"(ww));
        asm("fma.rn.f32x2 %0, %1, %2, %0;" : "+l"(a45) : "l"(p2),   "l"(ww));
        asm("fma.rn.f32x2 %0, %1, %2, %0;" : "+l"(a67) : "l"(p3),   "l"(ww));
        asm("fma.rn.f32x2 %0, %1, %2, %0;" : "+l"(a89) : "l"(p4),   "l"(ww));
    }
    {   // packed stores, lane stride 1 (conflict-free STS.64)
        u64* pp = psum + w * SLOTS + k;
        pp[0 * H] = a01;
        pp[1 * H] = a23;
        pp[2 * H] = a45;
        pp[3 * H] = a67;
        pp[4 * H] = a89;
    }
    __syncthreads();

    // ---- local reduce over 4 warps + DSMEM push into CTA0 ----
    {
        auto reduce_push = [&](int slot) {
            u64 q0 = psum[0 * SLOTS + slot];
            u64 q1 = psum[1 * SLOTS + slot];
            u64 q2 = psum[2 * SLOTS + slot];
            u64 q3 = psum[3 * SLOTS + slot];
            asm("add.rn.f32x2 %0, %0, %1;" : "+l"(q0) : "l"(q1));
            asm("add.rn.f32x2 %0, %0, %1;" : "+l"(q2) : "l"(q3));
            asm("add.rn.f32x2 %0, %0, %1;" : "+l"(q0) : "l"(q2));
            unsigned la = smem_u32(&gather[rank * SLOTS + slot]);
            unsigned ra;
            asm("mapa.shared::cluster.u32 %0, %1, 0;" : "=r"(ra) : "r"(la));
            asm volatile("st.shared::cluster.b64 [%0], %1;"
                         :: "r"(ra), "l"(q0) : "memory");
        };
        reduce_push(t);
        if (t < SLOTS - THREADS) reduce_push(THREADS + t);  // slots 128..159
    }

    // ---- cluster barrier: DSMEM writes -> visible to CTA0 ----
    asm volatile("barrier.cluster.arrive.aligned;" ::: "memory");
    asm volatile("barrier.cluster.wait.aligned;" ::: "memory");

    if (rank != 0) return;

    // ---- CTA0: combine 4 CTA partials, bias, relu ----
    {
        auto finish = [&](int slot) {
            u64 q0 = gather[0 * SLOTS + slot];
            u64 q1 = gather[1 * SLOTS + slot];
            u64 q2 = gather[2 * SLOTS + slot];
            u64 q3 = gather[3 * SLOTS + slot];
            asm("add.rn.f32x2 %0, %0, %1;" : "+l"(q0) : "l"(q1));
            asm("add.rn.f32x2 %0, %0, %1;" : "+l"(q2) : "l"(q3));
            asm("add.rn.f32x2 %0, %0, %1;" : "+l"(q0) : "l"(q2));
            unsigned lo, hi;
            asm("mov.b64 {%0, %1}, %2;" : "=r"(lo), "=r"(hi) : "l"(q0));
            const int p = slot >> 5, kk = slot & 31;    // kk == k for our slots
            h[(2 * p) * H + kk] = fmaxf(__uint_as_float(lo) + b1r, 0.0f);
            if (p < 4)
                h[(2 * p + 1) * H + kk] = fmaxf(__uint_as_float(hi) + b1r, 0.0f);
        };
        finish(t);
        if (t < SLOTS - THREADS) finish(THREADS + t);
    }
    __syncthreads();

    // ---- tail: warp c computes output column c ----
    {
        float s = 0.f;
#pragma unroll
        for (int r = 0; r < N; r++) s += h[r * H + k];   // CF (stride 32)

        float v = s * w2c;
#pragma unroll
        for (int off = 16; off; off >>= 1)               // fixed xor tree
            v += __shfl_xor_sync(0xffffffffu, v, off);

        float val = FACT8 * fmaf((float)N, b2c, v);
        if (k < N) out[k * 4 + w] = val;                 // out[r][c]
    }
}

extern "C" void kernel_launch(void* const* d_in, const int* in_sizes, int n_in,
                              void* d_out, int out_size) {
    // metadata order: x[9,512], W1[512,32], b1[32], W2[32,4], b2[4], perms (unused)
    const float* x  = (const float*)d_in[0];
    const float* W1 = (const float*)d_in[1];
    const float* b1 = (const float*)d_in[2];
    const float* W2 = (const float*)d_in[3];
    const float* b2 = (const float*)d_in[4];
    float* out = (float*)d_out;

    sym_kernel<<<CLUSTER, THREADS>>>(x, W1, b1, W2, b2, out);
}

// round 9
// speedup vs baseline: 1.0049x; 1.0049x over previous
#include <cuda_runtime.h>

// out[i,c] = 8! * sum_j ( relu(x @ W1 + b1) @ W2 + b2 )[j,c]   (row-constant)
//
// R9: single CTA (cluster reverted: it improved ncu kernel time but not the
// bench, which is launch-overhead floored). R7 body with a leaner serial
// tail: packed b1 add, h kept packed [k][pair] (STS.64 / 5x LDS.64),
// packed-add tail with the row-8 pad half excluded analytically.

static constexpr int N = 9;
static constexpr int D = 512;
static constexpr int H = 32;
static constexpr int THREADS = 512;
static constexpr int WARPS = 16;
static constexpr int DPW = D / WARPS;     // 32 d-values per warp
static constexpr int XPAD = 12;           // floats per xT row (48B)
static constexpr int PAIRS = 5;           // (0,1)(2,3)(4,5)(6,7)(8,pad)
static constexpr float FACT8 = 40320.0f;  // (N-1)!

typedef unsigned long long u64;

__global__ void __launch_bounds__(THREADS, 1)
sym_kernel(const float* __restrict__ x,
           const float* __restrict__ W1,
           const float* __restrict__ b1,
           const float* __restrict__ W2,
           const float* __restrict__ b2,
           float* __restrict__ out) {
    __shared__ __align__(16) float xT[D * XPAD];          // xT[d][r]
    __shared__ __align__(16) u64 psum[WARPS * PAIRS * H]; // [w][p*H + k]
    __shared__ __align__(16) u64 hp[H * PAIRS];           // [k][p] packed relu'd

    const int t = threadIdx.x;
    const int w = t >> 5;   // warp 0..15
    const int k = t & 31;   // lane

    // ---- per-warp prefetch (no CTA barrier before mainloop) ----
#pragma unroll
    for (int r = 0; r < N; r++)
        xT[t * XPAD + r] = x[r * D + t];
    xT[t * XPAD + 9] = 0.0f;   // pad slot read by the packed row-8 accumulator

    // W1 chunk -> packed (wv,wv) registers (packing in LDG shadow)
    u64 wpack[DPW];
    const float* W1p = W1 + (w * DPW) * H + k;
#pragma unroll
    for (int i = 0; i < DPW; i++) {
        unsigned wu = __float_as_uint(W1p[i * H]);
        asm("mov.b64 %0, {%1, %1};" : "=l"(wpack[i]) : "r"(wu));
    }

    // phase operands
    u64 b1p = 0;                      // (b1[k], b1[k]) for reduce warps
    if (w < PAIRS) {
        unsigned bu = __float_as_uint(b1[k]);
        asm("mov.b64 %0, {%1, %1};" : "=l"(b1p) : "r"(bu));
    }
    float w2c = 0.f, b2c = 0.f;
    if (w < 4) {                      // tail: warp c owns output column c
        w2c = W2[k * 4 + w];
        b2c = b2[w];
    }
    __syncwarp();   // xT slice is produced/consumed by this warp only

    // ---- rank-1-update partial dots: 5 packed f32x2 accumulators ----
    u64 a01 = 0, a23 = 0, a45 = 0, a67 = 0, a89 = 0;
    const float* xrow = xT + (w * DPW) * XPAD;
#pragma unroll
    for (int i = 0; i < DPW; i++) {
        const float* xp = xrow + i * XPAD;            // 48B-aligned
        ulonglong2 p0 = *(const ulonglong2*)(xp);     // rows 0..3 (bcast)
        u64 p2 = *(const u64*)(xp + 4);               // rows 4,5
        u64 p3 = *(const u64*)(xp + 6);               // rows 6,7
        u64 p4 = *(const u64*)(xp + 8);               // rows 8,pad
        u64 ww = wpack[i];
        asm("fma.rn.f32x2 %0, %1, %2, %0;" : "+l"(a01) : "l"(p0.x), "l"(ww));
        asm("fma.rn.f32x2 %0, %1, %2, %0;" : "+l"(a23) : "l"(p0.y), "l"(ww));
        asm("fma.rn.f32x2 %0, %1, %2, %0;" : "+l"(a45) : "l"(p2),   "l"(ww));
        asm("fma.rn.f32x2 %0, %1, %2, %0;" : "+l"(a67) : "l"(p3),   "l"(ww));
        asm("fma.rn.f32x2 %0, %1, %2, %0;" : "+l"(a89) : "l"(p4),   "l"(ww));
    }
    {   // packed stores, lane stride 1 (conflict-free STS.64)
        u64* pp = psum + w * (PAIRS * H) + k;
        pp[0 * H] = a01;
        pp[1 * H] = a23;
        pp[2 * H] = a45;
        pp[3 * H] = a67;
        pp[4 * H] = a89;
    }

    // producers signal and exit; consumers wait
    if (w >= PAIRS) {
        asm volatile("bar.arrive 0, %0;" :: "r"(THREADS) : "memory");
        return;
    }
    asm volatile("bar.sync 0, %0;" :: "r"(THREADS) : "memory");

    // ---- reduce 16 warp partials for pair w, lane k (fixed tree) ----
    {
        u64 q[WARPS];
#pragma unroll
        for (int j = 0; j < WARPS; j++)
            q[j] = psum[j * (PAIRS * H) + w * H + k];   // LDS.64, CF
#pragma unroll
        for (int st = 1; st < WARPS; st <<= 1)
#pragma unroll
            for (int j = 0; j < WARPS; j += 2 * st)
                asm("add.rn.f32x2 %0, %0, %1;" : "+l"(q[j]) : "l"(q[j + st]));
        // + packed bias, relu both halves, store packed
        asm("add.rn.f32x2 %0, %0, %1;" : "+l"(q[0]) : "l"(b1p));
        unsigned lo, hi;
        asm("mov.b64 {%0, %1}, %2;" : "=r"(lo), "=r"(hi) : "l"(q[0]));
        float hl = fmaxf(__uint_as_float(lo), 0.0f);
        float hh = fmaxf(__uint_as_float(hi), 0.0f);
        u64 hq;
        asm("mov.b64 %0, {%1, %2};" : "=l"(hq)
            : "r"(__float_as_uint(hl)), "r"(__float_as_uint(hh)));
        hp[k * PAIRS + w] = hq;      // lane stride 5 u64 -> <=2-way
    }
    asm volatile("bar.sync 1, %0;" :: "r"(PAIRS * H) : "memory");  // warps 0..4
    if (w == 4) return;

    // ---- tail: warp c computes output column c ----
    {
        const u64* hk = hp + k * PAIRS;
        u64 s01 = hk[0], s23 = hk[1], s45 = hk[2], s67 = hk[3], s8p = hk[4];
        asm("add.rn.f32x2 %0, %0, %1;" : "+l"(s01) : "l"(s23));
        asm("add.rn.f32x2 %0, %0, %1;" : "+l"(s45) : "l"(s67));
        asm("add.rn.f32x2 %0, %0, %1;" : "+l"(s01) : "l"(s45));
        unsigned lo, hi, l8, h8;
        asm("mov.b64 {%0, %1}, %2;" : "=r"(lo), "=r"(hi) : "l"(s01));
        asm("mov.b64 {%0, %1}, %2;" : "=r"(l8), "=r"(h8) : "l"(s8p));
        // row-8 pair's hi half is relu(b1) garbage from the pad: exclude it
        float s = (__uint_as_float(lo) + __uint_as_float(hi)) + __uint_as_float(l8);

        float v = s * w2c;
#pragma unroll
        for (int off = 16; off; off >>= 1)   // fixed xor tree
            v += __shfl_xor_sync(0xffffffffu, v, off);

        float val = FACT8 * fmaf((float)N, b2c, v);
        if (k < N) out[k * 4 + w] = val;     // out[r][c], r = lane
    }
}

extern "C" void kernel_launch(void* const* d_in, const int* in_sizes, int n_in,
                              void* d_out, int out_size) {
    // metadata order: x[9,512], W1[512,32], b1[32], W2[32,4], b2[4], perms (unused)
    const float* x  = (const float*)d_in[0];
    const float* W1 = (const float*)d_in[1];
    const float* b1 = (const float*)d_in[2];
    const float* W2 = (const float*)d_in[3];
    const float* b2 = (const float*)d_in[4];
    float* out = (float*)d_out;

    sym_kernel<<<1, THREADS>>>(x, W1, b1, W2, b2, out);
}